// round 14
// baseline (speedup 1.0000x reference)
#include <cuda_runtime.h>
#include <cuda_fp16.h>
#include <cstdint>
#include <math.h>

#define B_PTS   262144
#define HIDDEN  512
#define DIM_IN  48

// ---------------- scratch (static device arrays; no allocs) ----------------
__device__ __half g_feats[(size_t)B_PTS * DIM_IN];          // 24 MB fp16
__device__ __half g_h[(size_t)B_PTS * HIDDEN];              // 256 MB fp16
__device__ __half g_w2h[HIDDEN * HIDDEN];                   // [N][K] K-major fp16
__device__ __half g_w1h[HIDDEN * DIM_IN];                   // [N=512][K=48] fp16

__constant__ float c_sres[16] = {16,22,30,42,58,80,111,154,212,294,406,561,776,1072,1482,2048};
__constant__ float c_tres[8]  = {8,16,32,64,128,256,512,1024};

__device__ __forceinline__ void cp16(void* s, const void* g) {
    uint32_t sa = (uint32_t)__cvta_generic_to_shared(s);
    asm volatile("cp.async.cg.shared.global [%0], [%1], 16;" :: "r"(sa), "l"(g));
}
__device__ __forceinline__ void cp_commit() { asm volatile("cp.async.commit_group;"); }
template<int N> __device__ __forceinline__ void cp_wait() {
    asm volatile("cp.async.wait_group %0;" :: "n"(N));
}
__device__ __forceinline__ uint32_t smem_u32(const void* p) {
    return (uint32_t)__cvta_generic_to_shared(p);
}
__device__ __forceinline__ void ldsm_x4(uint32_t& r0, uint32_t& r1, uint32_t& r2, uint32_t& r3,
                                        uint32_t addr) {
    asm volatile("ldmatrix.sync.aligned.m8n8.x4.shared.b16 {%0,%1,%2,%3}, [%4];"
                 : "=r"(r0), "=r"(r1), "=r"(r2), "=r"(r3) : "r"(addr));
}
__device__ __forceinline__ void mma16816(float* c, const uint32_t* a, uint32_t b0, uint32_t b1) {
    asm volatile(
        "mma.sync.aligned.m16n8k16.row.col.f32.f16.f16.f32 "
        "{%0,%1,%2,%3},{%4,%5,%6,%7},{%8,%9},{%0,%1,%2,%3};"
        : "+f"(c[0]), "+f"(c[1]), "+f"(c[2]), "+f"(c[3])
        : "r"(a[0]), "r"(a[1]), "r"(a[2]), "r"(a[3]), "r"(b0), "r"(b1));
}
__device__ __forceinline__ float gelu_exact(float y) {
    return 0.5f * y * (1.0f + erff(y * 0.70710678118654752f));
}

// ---------------- kernel 0a: transpose + fp16-round w2 -> g_w2h[N][K] ----------------
__global__ void prep_w2_kernel(const float* __restrict__ w2) {
    __shared__ float tile[32][33];
    int x = blockIdx.x * 32 + threadIdx.x;   // n
    int y = blockIdx.y * 32 + threadIdx.y;   // k
    tile[threadIdx.y][threadIdx.x] = w2[y * 512 + x];
    __syncthreads();
    int ko = blockIdx.y * 32 + threadIdx.x;  // k
    int no = blockIdx.x * 32 + threadIdx.y;  // n
    g_w2h[no * 512 + ko] = __float2half_rn(tile[threadIdx.x][threadIdx.y]);
}

// ---------------- kernel 0b: transpose + fp16-round w1 -> g_w1h[N=512][K=48] ---------
__global__ void prep_w1_kernel(const float* __restrict__ w1) {
    int i = blockIdx.x * 256 + threadIdx.x;   // i over 512*48
    int n = i / 48, k = i % 48;
    g_w1h[i] = __float2half_rn(w1[k * 512 + n]);
}

// ---------------- kernel 1: 4D hash-grid encode -> fp16 feats ----------------
__global__ __launch_bounds__(256) void encode_kernel(
    const float4* __restrict__ xyzt,
    const int* __restrict__ smask,
    const int* __restrict__ tmask,
    const float2* __restrict__ stab,
    const float2* __restrict__ ttab)
{
    int i = blockIdx.x * 256 + threadIdx.x;
    float4 p = xyzt[i];
    float sm = smask[i] ? 1.0f : 0.0f;
    float tm = tmask[i] ? 1.0f : 0.0f;

    float out[DIM_IN];

    #pragma unroll
    for (int l = 0; l < 16; l++) {
        float r = c_sres[l];
        float px = p.x * r, py = p.y * r, pz = p.z * r;
        float fx = floorf(px), fy = floorf(py), fz = floorf(pz);
        unsigned bx = (unsigned)fx, by = (unsigned)fy, bz = (unsigned)fz;
        float wx1 = px - fx, wy1 = py - fy, wz1 = pz - fz;
        float wx0 = 1.0f - wx1, wy0 = 1.0f - wy1, wz0 = 1.0f - wz1;
        const float2* tab = stab + (size_t)l * 524288;
        unsigned hy0 = by * 2654435761u, hy1 = (by + 1u) * 2654435761u;
        unsigned hz0 = bz * 805459861u,  hz1 = (bz + 1u) * 805459861u;
        float f0 = 0.0f, f1 = 0.0f;
        #pragma unroll
        for (int cz = 0; cz < 2; cz++) {
            unsigned hz = cz ? hz1 : hz0; float wz = cz ? wz1 : wz0;
            #pragma unroll
            for (int cy = 0; cy < 2; cy++) {
                unsigned hy = cy ? hy1 : hy0; float wy = cy ? wy1 : wy0;
                #pragma unroll
                for (int cx = 0; cx < 2; cx++) {
                    unsigned idx = ((bx + (unsigned)cx) ^ hy ^ hz) & 524287u;
                    float w = (cx ? wx1 : wx0) * wy * wz;
                    float2 v = __ldg(tab + idx);
                    f0 += w * v.x;
                    f1 += w * v.y;
                }
            }
        }
        out[2 * l]     = f0 * sm;
        out[2 * l + 1] = f1 * sm;
    }

    #pragma unroll
    for (int l = 0; l < 8; l++) {
        float r = c_tres[l];
        float pt = p.w * r;
        float ft = floorf(pt);
        unsigned bt = (unsigned)ft;
        float w1v = pt - ft, w0v = 1.0f - w1v;
        const float2* tab = ttab + (size_t)l * 131072;
        float2 v0 = __ldg(tab + (bt & 131071u));
        float2 v1 = __ldg(tab + ((bt + 1u) & 131071u));
        out[32 + 2 * l]     = (w0v * v0.x + w1v * v1.x) * tm;
        out[32 + 2 * l + 1] = (w0v * v0.y + w1v * v1.y) * tm;
    }

    uint32_t w[24];
    #pragma unroll
    for (int j = 0; j < 24; j++) {
        __half2 h2 = __floats2half2_rn(out[2*j], out[2*j+1]);
        w[j] = *(uint32_t*)&h2;
    }
    uint4* dst = (uint4*)(g_feats + (size_t)i * DIM_IN);
    #pragma unroll
    for (int q = 0; q < 6; q++)
        dst[q] = make_uint4(w[4*q], w[4*q+1], w[4*q+2], w[4*q+3]);
}

// ---------------- kernel 2: GEMM1 (48->512) fp16 mma + LN + GELU -> fp16 h ----------
#define KP 56
#define M1_SMEM_BYTES (512*KP*2 + 32*KP*2 + 32*8*8 + 256)
__global__ __launch_bounds__(256, 2) void mlp1_kernel(
    const float* __restrict__ b1,
    const float* __restrict__ lng, const float* __restrict__ lnb)
{
    extern __shared__ __align__(16) char sm1[];
    __half* w1s = (__half*)sm1;               // [512][KP]
    __half* fs  = w1s + 512 * KP;             // [32][KP]
    float2* red = (float2*)(fs + 32 * KP);    // [32][8]
    float*  mus = (float*)(red + 32 * 8);
    float*  rss = mus + 32;
    __half* hstage = (__half*)sm1;            // overlay w1s after mainloop: [32][520]

    int tid = threadIdx.x;
    int wid = tid >> 5, lane = tid & 31;

    for (int q = tid; q < 3072; q += 256) {
        int r = q / 6, cc = q % 6;
        cp16(w1s + r * KP + cc * 8, g_w1h + r * 48 + cc * 8);
    }
    {
        const __half* fg = g_feats + (size_t)blockIdx.x * 32 * 48;
        if (tid < 192) {
            int r = tid / 6, cc = tid % 6;
            cp16(fs + r * KP + cc * 8, fg + r * 48 + cc * 8);
        }
    }
    cp_commit(); cp_wait<0>();
    __syncthreads();

    int g = lane >> 2, t4 = lane & 3;
    int lrow = lane & 15, lcol = (lane >> 4) * 8;
    uint32_t fsb = smem_u32(fs), wsb = smem_u32(w1s);

    float c[2][8][4] = {};

    #pragma unroll
    for (int ks = 0; ks < 3; ks++) {
        uint32_t a[2][4];
        #pragma unroll
        for (int mf = 0; mf < 2; mf++) {
            uint32_t ad = fsb + (uint32_t)(((mf * 16 + lrow) * KP + ks * 16 + lcol) * 2);
            ldsm_x4(a[mf][0], a[mf][1], a[mf][2], a[mf][3], ad);
        }
        uint32_t b[4][4];
        #pragma unroll
        for (int nq = 0; nq < 4; nq++) {
            uint32_t bd = wsb + (uint32_t)(((wid * 64 + nq * 16 + lrow) * KP + ks * 16 + lcol) * 2);
            ldsm_x4(b[nq][0], b[nq][1], b[nq][2], b[nq][3], bd);
        }
        #pragma unroll
        for (int mf = 0; mf < 2; mf++)
            #pragma unroll
            for (int nq = 0; nq < 4; nq++) {
                mma16816(c[mf][nq * 2 + 0], a[mf], b[nq][0], b[nq][2]);
                mma16816(c[mf][nq * 2 + 1], a[mf], b[nq][1], b[nq][3]);
            }
    }

    #pragma unroll
    for (int nf = 0; nf < 8; nf++) {
        int col = wid * 64 + nf * 8 + 2 * t4;
        float2 bbv = *(const float2*)(b1 + col);
        #pragma unroll
        for (int mf = 0; mf < 2; mf++) {
            c[mf][nf][0] += bbv.x; c[mf][nf][1] += bbv.y;
            c[mf][nf][2] += bbv.x; c[mf][nf][3] += bbv.y;
        }
    }

    {
        float s[4] = {0,0,0,0}, s2[4] = {0,0,0,0};
        #pragma unroll
        for (int nf = 0; nf < 8; nf++) {
            #pragma unroll
            for (int mf = 0; mf < 2; mf++) {
                float v0 = c[mf][nf][0], v1 = c[mf][nf][1];
                float v2 = c[mf][nf][2], v3 = c[mf][nf][3];
                s[mf*2+0] += v0 + v1;  s2[mf*2+0] += v0*v0 + v1*v1;
                s[mf*2+1] += v2 + v3;  s2[mf*2+1] += v2*v2 + v3*v3;
            }
        }
        #pragma unroll
        for (int r = 0; r < 4; r++) {
            #pragma unroll
            for (int off = 1; off < 4; off <<= 1) {
                s[r]  += __shfl_xor_sync(0xffffffffu, s[r],  off);
                s2[r] += __shfl_xor_sync(0xffffffffu, s2[r], off);
            }
        }
        if (t4 == 0) {
            red[(g     ) * 8 + wid] = make_float2(s[0], s2[0]);
            red[(g + 8 ) * 8 + wid] = make_float2(s[1], s2[1]);
            red[(g + 16) * 8 + wid] = make_float2(s[2], s2[2]);
            red[(g + 24) * 8 + wid] = make_float2(s[3], s2[3]);
        }
    }
    __syncthreads();
    if (tid < 32) {
        float s = 0.0f, s2 = 0.0f;
        #pragma unroll
        for (int j = 0; j < 8; j++) {
            float2 v = red[tid * 8 + j];
            s += v.x; s2 += v.y;
        }
        float mu = s * (1.0f / 512.0f);
        float var = s2 * (1.0f / 512.0f) - mu * mu;
        mus[tid] = mu;
        rss[tid] = rsqrtf(var + 1e-5f);
    }
    __syncthreads();   // ldmatrix reads of w1s done -> safe to overlay

    {
        float mu[4], rs[4];
        #pragma unroll
        for (int r = 0; r < 4; r++) { mu[r] = mus[g + 8*r]; rs[r] = rss[g + 8*r]; }
        #pragma unroll
        for (int nf = 0; nf < 8; nf++) {
            int col = wid * 64 + nf * 8 + 2 * t4;
            float2 lgv = *(const float2*)(lng + col);
            float2 lbv = *(const float2*)(lnb + col);
            #pragma unroll
            for (int mf = 0; mf < 2; mf++) {
                int r0 = mf * 2, r1 = mf * 2 + 1;
                float y0 = (c[mf][nf][0] - mu[r0]) * rs[r0] * lgv.x + lbv.x;
                float y1 = (c[mf][nf][1] - mu[r0]) * rs[r0] * lgv.y + lbv.y;
                float y2 = (c[mf][nf][2] - mu[r1]) * rs[r1] * lgv.x + lbv.x;
                float y3 = (c[mf][nf][3] - mu[r1]) * rs[r1] * lgv.y + lbv.y;
                __half2 h0 = __floats2half2_rn(gelu_exact(y0), gelu_exact(y1));
                __half2 h1 = __floats2half2_rn(gelu_exact(y2), gelu_exact(y3));
                *(__half2*)(hstage + (mf * 16 + g) * 520 + col)     = h0;
                *(__half2*)(hstage + (mf * 16 + g + 8) * 520 + col) = h1;
            }
        }
    }
    __syncthreads();
    {
        uint4* hout = (uint4*)(g_h + (size_t)blockIdx.x * 32 * 512);
        #pragma unroll
        for (int i = 0; i < 8; i++) {
            int q = tid + i * 256;
            int r = q >> 6, cc = q & 63;
            hout[q] = *(uint4*)(hstage + r * 520 + cc * 8);
        }
    }
}

// ---------------- kernel 3: GEMM2 (512x512) fp16 mma — 128x256 CTA, 16 warps ------
// 512 threads, warp tile 32x64 (wm = wid&3, wn = wid>>2). CK=32, 3 stages,
// R9 single-barrier pipeline. 2 CTAs/SM -> 32 warps/SM.
#define AST 40
#define B_OFF_H (128 * AST)                       // A block rows 0..127
#define STAGE_HALVES ((128 + 256) * AST)          // A + B(256 n-rows)
#define STAGE_BYTES  (STAGE_HALVES * 2)           // 30720
#define SMEM2_BYTES  (3 * STAGE_BYTES)            // 92160

__global__ __launch_bounds__(512, 2) void mlp2_kernel(
    const float* __restrict__ b2, float* __restrict__ out)
{
    extern __shared__ __half sm2[];
    uint32_t smem_base = smem_u32(sm2);

    int tid = threadIdx.x;
    int wid = tid >> 5, lane = tid & 31;
    int bn = blockIdx.x, bm = blockIdx.y;
    const __half* Ag = g_h   + (size_t)bm * 128 * 512;
    const __half* Bg = g_w2h + (size_t)bn * 256 * 512;

    auto load = [&](int kt, int s) {
        __half* dstA = sm2 + (size_t)s * STAGE_HALVES;
        {   // A: 128 rows x 4 chunks = 512 chunks, 1 per thread
            int r = tid >> 2, cc = tid & 3;
            cp16(dstA + r * AST + cc * 8, Ag + (size_t)r * 512 + kt * 32 + cc * 8);
        }
        __half* dstB = dstA + B_OFF_H;
        #pragma unroll
        for (int i = 0; i < 2; i++) {   // B: 256 rows x 4 chunks = 1024 chunks
            int q = tid + i * 512;
            int r = q >> 2, cc = q & 3;
            cp16(dstB + r * AST + cc * 8, Bg + (size_t)r * 512 + kt * 32 + cc * 8);
        }
    };

    load(0, 0); cp_commit();
    load(1, 1); cp_commit();

    int wm = wid & 3, wn = wid >> 2;          // wm 0..3 (rows), wn 0..3 (64-col slabs)
    int g = lane >> 2, t4 = lane & 3;
    int lrow = lane & 15, lcol = (lane >> 4) * 8;

    float c[2][8][4] = {};

    for (int kt = 0; kt < 16; kt++) {
        if (kt < 15) cp_wait<1>(); else cp_wait<0>();
        __syncthreads();                       // stage kt visible; stage (kt+2)%3 free
        if (kt + 2 < 16) { load(kt + 2, (kt + 2) % 3); cp_commit(); }

        uint32_t base = smem_base + (uint32_t)((kt % 3) * STAGE_BYTES);

        #pragma unroll
        for (int ks = 0; ks < 2; ks++) {
            uint32_t a[2][4];
            #pragma unroll
            for (int mf = 0; mf < 2; mf++) {
                uint32_t ad = base + ((wm * 32 + mf * 16 + lrow) * AST + ks * 16 + lcol) * 2;
                ldsm_x4(a[mf][0], a[mf][1], a[mf][2], a[mf][3], ad);
            }
            uint32_t b[4][4];
            #pragma unroll
            for (int nq = 0; nq < 4; nq++) {
                uint32_t bd = base + B_OFF_H * 2 +
                              ((wn * 64 + nq * 16 + lrow) * AST + ks * 16 + lcol) * 2;
                ldsm_x4(b[nq][0], b[nq][1], b[nq][2], b[nq][3], bd);
            }
            #pragma unroll
            for (int mf = 0; mf < 2; mf++)
                #pragma unroll
                for (int nq = 0; nq < 4; nq++) {
                    mma16816(c[mf][nq * 2 + 0], a[mf], b[nq][0], b[nq][2]);
                    mma16816(c[mf][nq * 2 + 1], a[mf], b[nq][1], b[nq][3]);
                }
        }
    }

    #pragma unroll
    for (int mf = 0; mf < 2; mf++) {
        #pragma unroll
        for (int nf = 0; nf < 8; nf++) {
            int row = bm * 128 + wm * 32 + mf * 16 + g;
            int col = bn * 256 + wn * 64 + nf * 8 + 2 * t4;
            float2 bbv = *(const float2*)(b2 + col);
            float2 v0 = make_float2(c[mf][nf][0] + bbv.x, c[mf][nf][1] + bbv.y);
            float2 v1 = make_float2(c[mf][nf][2] + bbv.x, c[mf][nf][3] + bbv.y);
            *(float2*)(out + (size_t)row * 512 + col) = v0;
            *(float2*)(out + (size_t)(row + 8) * 512 + col) = v1;
        }
    }
}

// ---------------- launch ----------------
extern "C" void kernel_launch(void* const* d_in, const int* in_sizes, int n_in,
                              void* d_out, int out_size)
{
    const float* xyzt  = (const float*)d_in[0];
    const int*   smask = (const int*)d_in[1];
    const int*   tmask = (const int*)d_in[2];
    const float* stab  = (const float*)d_in[3];
    const float* ttab  = (const float*)d_in[4];
    const float* w1    = (const float*)d_in[5];
    const float* b1    = (const float*)d_in[6];
    const float* lng   = (const float*)d_in[7];
    const float* lnb   = (const float*)d_in[8];
    const float* w2    = (const float*)d_in[9];
    const float* b2    = (const float*)d_in[10];
    float*       out   = (float*)d_out;

    cudaFuncSetAttribute(mlp1_kernel, cudaFuncAttributeMaxDynamicSharedMemorySize,
                         M1_SMEM_BYTES);
    cudaFuncSetAttribute(mlp2_kernel, cudaFuncAttributeMaxDynamicSharedMemorySize,
                         SMEM2_BYTES);

    dim3 tb(32, 32);
    dim3 tg(16, 16);
    prep_w2_kernel<<<tg, tb>>>(w2);
    prep_w1_kernel<<<(HIDDEN * DIM_IN) / 256, 256>>>(w1);
    encode_kernel<<<B_PTS / 256, 256>>>((const float4*)xyzt, smask, tmask,
                                        (const float2*)stab, (const float2*)ttab);
    mlp1_kernel<<<B_PTS / 32, 256, M1_SMEM_BYTES>>>(b1, lng, lnb);
    dim3 g2(HIDDEN / 256, B_PTS / 128);   // (2, 2048)
    mlp2_kernel<<<g2, 512, SMEM2_BYTES>>>(b2, out);
}

// round 15
// speedup vs baseline: 2.1631x; 2.1631x over previous
#include <cuda_runtime.h>
#include <cuda_fp16.h>
#include <cstdint>
#include <math.h>

#define B_PTS   262144
#define HIDDEN  512
#define DIM_IN  48

// ---------------- scratch (static device arrays; no allocs) ----------------
__device__ __half g_feats[(size_t)B_PTS * DIM_IN];          // 24 MB fp16
__device__ __half g_h[(size_t)B_PTS * HIDDEN];              // 256 MB fp16
__device__ __half g_w2h[HIDDEN * HIDDEN];                   // [N][K] K-major fp16
__device__ __half g_w1h[HIDDEN * DIM_IN];                   // [N=512][K=48] fp16

__constant__ float c_sres[16] = {16,22,30,42,58,80,111,154,212,294,406,561,776,1072,1482,2048};
__constant__ float c_tres[8]  = {8,16,32,64,128,256,512,1024};

__device__ __forceinline__ void cp16(void* s, const void* g) {
    uint32_t sa = (uint32_t)__cvta_generic_to_shared(s);
    asm volatile("cp.async.cg.shared.global [%0], [%1], 16;" :: "r"(sa), "l"(g));
}
__device__ __forceinline__ void cp_commit() { asm volatile("cp.async.commit_group;"); }
template<int N> __device__ __forceinline__ void cp_wait() {
    asm volatile("cp.async.wait_group %0;" :: "n"(N));
}
__device__ __forceinline__ uint32_t smem_u32(const void* p) {
    return (uint32_t)__cvta_generic_to_shared(p);
}
__device__ __forceinline__ void ldsm_x4(uint32_t& r0, uint32_t& r1, uint32_t& r2, uint32_t& r3,
                                        uint32_t addr) {
    asm volatile("ldmatrix.sync.aligned.m8n8.x4.shared.b16 {%0,%1,%2,%3}, [%4];"
                 : "=r"(r0), "=r"(r1), "=r"(r2), "=r"(r3) : "r"(addr));
}
__device__ __forceinline__ void mma16816(float* c, const uint32_t* a, uint32_t b0, uint32_t b1) {
    asm volatile(
        "mma.sync.aligned.m16n8k16.row.col.f32.f16.f16.f32 "
        "{%0,%1,%2,%3},{%4,%5,%6,%7},{%8,%9},{%0,%1,%2,%3};"
        : "+f"(c[0]), "+f"(c[1]), "+f"(c[2]), "+f"(c[3])
        : "r"(a[0]), "r"(a[1]), "r"(a[2]), "r"(a[3]), "r"(b0), "r"(b1));
}
__device__ __forceinline__ float gelu_exact(float y) {
    return 0.5f * y * (1.0f + erff(y * 0.70710678118654752f));
}

// ---------------- kernel 0: prep both weights (w2 transpose + w1 transpose) --------
// grid (16,16): blocks with by<16 handle w2 32x32 tiles; one extra pass handles w1
// via dedicated range. Simpler: single kernel, first 256 blocks do w2 tiles, rest w1.
__global__ void prep_weights_kernel(const float* __restrict__ w2,
                                    const float* __restrict__ w1) {
    __shared__ float tile[32][33];
    int b = blockIdx.x;
    if (b < 256) {                 // w2: 16x16 tiles of 32x32
        int bx = b & 15, by = b >> 4;
        int x = bx * 32 + threadIdx.x;   // n
        int y = by * 32 + threadIdx.y;   // k
        tile[threadIdx.y][threadIdx.x] = w2[y * 512 + x];
        __syncthreads();
        int ko = by * 32 + threadIdx.x;
        int no = bx * 32 + threadIdx.y;
        g_w2h[no * 512 + ko] = __float2half_rn(tile[threadIdx.x][threadIdx.y]);
    } else {                       // w1: 24 blocks x 1024 elems = 24576
        int i = (b - 256) * 1024 + threadIdx.y * 32 + threadIdx.x;
        int n = i / 48, k = i % 48;
        g_w1h[i] = __float2half_rn(w1[k * 512 + n]);
    }
}

// ---------------- kernel 1: 4D hash-grid encode -> fp16 feats ----------------
__global__ __launch_bounds__(256) void encode_kernel(
    const float4* __restrict__ xyzt,
    const int* __restrict__ smask,
    const int* __restrict__ tmask,
    const float2* __restrict__ stab,
    const float2* __restrict__ ttab)
{
    int i = blockIdx.x * 256 + threadIdx.x;
    float4 p = xyzt[i];
    float sm = smask[i] ? 1.0f : 0.0f;
    float tm = tmask[i] ? 1.0f : 0.0f;

    float out[DIM_IN];

    #pragma unroll
    for (int l = 0; l < 16; l++) {
        float r = c_sres[l];
        float px = p.x * r, py = p.y * r, pz = p.z * r;
        float fx = floorf(px), fy = floorf(py), fz = floorf(pz);
        unsigned bx = (unsigned)fx, by = (unsigned)fy, bz = (unsigned)fz;
        float wx1 = px - fx, wy1 = py - fy, wz1 = pz - fz;
        float wx0 = 1.0f - wx1, wy0 = 1.0f - wy1, wz0 = 1.0f - wz1;
        const float2* tab = stab + (size_t)l * 524288;
        unsigned hy0 = by * 2654435761u, hy1 = (by + 1u) * 2654435761u;
        unsigned hz0 = bz * 805459861u,  hz1 = (bz + 1u) * 805459861u;
        float f0 = 0.0f, f1 = 0.0f;
        #pragma unroll
        for (int cz = 0; cz < 2; cz++) {
            unsigned hz = cz ? hz1 : hz0; float wz = cz ? wz1 : wz0;
            #pragma unroll
            for (int cy = 0; cy < 2; cy++) {
                unsigned hy = cy ? hy1 : hy0; float wy = cy ? wy1 : wy0;
                #pragma unroll
                for (int cx = 0; cx < 2; cx++) {
                    unsigned idx = ((bx + (unsigned)cx) ^ hy ^ hz) & 524287u;
                    float w = (cx ? wx1 : wx0) * wy * wz;
                    float2 v = __ldg(tab + idx);
                    f0 += w * v.x;
                    f1 += w * v.y;
                }
            }
        }
        out[2 * l]     = f0 * sm;
        out[2 * l + 1] = f1 * sm;
    }

    #pragma unroll
    for (int l = 0; l < 8; l++) {
        float r = c_tres[l];
        float pt = p.w * r;
        float ft = floorf(pt);
        unsigned bt = (unsigned)ft;
        float w1v = pt - ft, w0v = 1.0f - w1v;
        const float2* tab = ttab + (size_t)l * 131072;
        float2 v0 = __ldg(tab + (bt & 131071u));
        float2 v1 = __ldg(tab + ((bt + 1u) & 131071u));
        out[32 + 2 * l]     = (w0v * v0.x + w1v * v1.x) * tm;
        out[32 + 2 * l + 1] = (w0v * v0.y + w1v * v1.y) * tm;
    }

    uint32_t w[24];
    #pragma unroll
    for (int j = 0; j < 24; j++) {
        __half2 h2 = __floats2half2_rn(out[2*j], out[2*j+1]);
        w[j] = *(uint32_t*)&h2;
    }
    uint4* dst = (uint4*)(g_feats + (size_t)i * DIM_IN);
    #pragma unroll
    for (int q = 0; q < 6; q++)
        dst[q] = make_uint4(w[4*q], w[4*q+1], w[4*q+2], w[4*q+3]);
}

// ---------------- kernel 2: GEMM1 (48->512) fp16 mma + LN + GELU -> fp16 h ----------
#define KP 56
#define M1_SMEM_BYTES (512*KP*2 + 32*KP*2 + 32*8*8 + 256)
__global__ __launch_bounds__(256, 2) void mlp1_kernel(
    const float* __restrict__ b1,
    const float* __restrict__ lng, const float* __restrict__ lnb)
{
    extern __shared__ __align__(16) char sm1[];
    __half* w1s = (__half*)sm1;               // [512][KP]
    __half* fs  = w1s + 512 * KP;             // [32][KP]
    float2* red = (float2*)(fs + 32 * KP);    // [32][8]
    float*  mus = (float*)(red + 32 * 8);
    float*  rss = mus + 32;
    __half* hstage = (__half*)sm1;            // overlay w1s after mainloop: [32][520]

    int tid = threadIdx.x;
    int wid = tid >> 5, lane = tid & 31;

    for (int q = tid; q < 3072; q += 256) {
        int r = q / 6, cc = q % 6;
        cp16(w1s + r * KP + cc * 8, g_w1h + r * 48 + cc * 8);
    }
    {
        const __half* fg = g_feats + (size_t)blockIdx.x * 32 * 48;
        if (tid < 192) {
            int r = tid / 6, cc = tid % 6;
            cp16(fs + r * KP + cc * 8, fg + r * 48 + cc * 8);
        }
    }
    cp_commit(); cp_wait<0>();
    __syncthreads();

    int g = lane >> 2, t4 = lane & 3;
    int lrow = lane & 15, lcol = (lane >> 4) * 8;
    uint32_t fsb = smem_u32(fs), wsb = smem_u32(w1s);

    float c[2][8][4] = {};

    #pragma unroll
    for (int ks = 0; ks < 3; ks++) {
        uint32_t a[2][4];
        #pragma unroll
        for (int mf = 0; mf < 2; mf++) {
            uint32_t ad = fsb + (uint32_t)(((mf * 16 + lrow) * KP + ks * 16 + lcol) * 2);
            ldsm_x4(a[mf][0], a[mf][1], a[mf][2], a[mf][3], ad);
        }
        uint32_t b[4][4];
        #pragma unroll
        for (int nq = 0; nq < 4; nq++) {
            uint32_t bd = wsb + (uint32_t)(((wid * 64 + nq * 16 + lrow) * KP + ks * 16 + lcol) * 2);
            ldsm_x4(b[nq][0], b[nq][1], b[nq][2], b[nq][3], bd);
        }
        #pragma unroll
        for (int mf = 0; mf < 2; mf++)
            #pragma unroll
            for (int nq = 0; nq < 4; nq++) {
                mma16816(c[mf][nq * 2 + 0], a[mf], b[nq][0], b[nq][2]);
                mma16816(c[mf][nq * 2 + 1], a[mf], b[nq][1], b[nq][3]);
            }
    }

    #pragma unroll
    for (int nf = 0; nf < 8; nf++) {
        int col = wid * 64 + nf * 8 + 2 * t4;
        float2 bbv = *(const float2*)(b1 + col);
        #pragma unroll
        for (int mf = 0; mf < 2; mf++) {
            c[mf][nf][0] += bbv.x; c[mf][nf][1] += bbv.y;
            c[mf][nf][2] += bbv.x; c[mf][nf][3] += bbv.y;
        }
    }

    {
        float s[4] = {0,0,0,0}, s2[4] = {0,0,0,0};
        #pragma unroll
        for (int nf = 0; nf < 8; nf++) {
            #pragma unroll
            for (int mf = 0; mf < 2; mf++) {
                float v0 = c[mf][nf][0], v1 = c[mf][nf][1];
                float v2 = c[mf][nf][2], v3 = c[mf][nf][3];
                s[mf*2+0] += v0 + v1;  s2[mf*2+0] += v0*v0 + v1*v1;
                s[mf*2+1] += v2 + v3;  s2[mf*2+1] += v2*v2 + v3*v3;
            }
        }
        #pragma unroll
        for (int r = 0; r < 4; r++) {
            #pragma unroll
            for (int off = 1; off < 4; off <<= 1) {
                s[r]  += __shfl_xor_sync(0xffffffffu, s[r],  off);
                s2[r] += __shfl_xor_sync(0xffffffffu, s2[r], off);
            }
        }
        if (t4 == 0) {
            red[(g     ) * 8 + wid] = make_float2(s[0], s2[0]);
            red[(g + 8 ) * 8 + wid] = make_float2(s[1], s2[1]);
            red[(g + 16) * 8 + wid] = make_float2(s[2], s2[2]);
            red[(g + 24) * 8 + wid] = make_float2(s[3], s2[3]);
        }
    }
    __syncthreads();
    if (tid < 32) {
        float s = 0.0f, s2 = 0.0f;
        #pragma unroll
        for (int j = 0; j < 8; j++) {
            float2 v = red[tid * 8 + j];
            s += v.x; s2 += v.y;
        }
        float mu = s * (1.0f / 512.0f);
        float var = s2 * (1.0f / 512.0f) - mu * mu;
        mus[tid] = mu;
        rss[tid] = rsqrtf(var + 1e-5f);
    }
    __syncthreads();   // ldmatrix reads of w1s done -> safe to overlay

    {
        float mu[4], rs[4];
        #pragma unroll
        for (int r = 0; r < 4; r++) { mu[r] = mus[g + 8*r]; rs[r] = rss[g + 8*r]; }
        #pragma unroll
        for (int nf = 0; nf < 8; nf++) {
            int col = wid * 64 + nf * 8 + 2 * t4;
            float2 lgv = *(const float2*)(lng + col);
            float2 lbv = *(const float2*)(lnb + col);
            #pragma unroll
            for (int mf = 0; mf < 2; mf++) {
                int r0 = mf * 2, r1 = mf * 2 + 1;
                float y0 = (c[mf][nf][0] - mu[r0]) * rs[r0] * lgv.x + lbv.x;
                float y1 = (c[mf][nf][1] - mu[r0]) * rs[r0] * lgv.y + lbv.y;
                float y2 = (c[mf][nf][2] - mu[r1]) * rs[r1] * lgv.x + lbv.x;
                float y3 = (c[mf][nf][3] - mu[r1]) * rs[r1] * lgv.y + lbv.y;
                __half2 h0 = __floats2half2_rn(gelu_exact(y0), gelu_exact(y1));
                __half2 h1 = __floats2half2_rn(gelu_exact(y2), gelu_exact(y3));
                *(__half2*)(hstage + (mf * 16 + g) * 520 + col)     = h0;
                *(__half2*)(hstage + (mf * 16 + g + 8) * 520 + col) = h1;
            }
        }
    }
    __syncthreads();
    {
        uint4* hout = (uint4*)(g_h + (size_t)blockIdx.x * 32 * 512);
        #pragma unroll
        for (int i = 0; i < 8; i++) {
            int q = tid + i * 256;
            int r = q >> 6, cc = q & 63;
            hout[q] = *(uint4*)(hstage + r * 520 + cc * 8);
        }
    }
}

// ---------------- kernel 3: GEMM2 (512x512) fp16 mma — R9 pipeline (proven) -------
// CTA 128x128, 8 warps of 32x64. CK=32, 3 stages, ONE barrier per k-iter.
#define AST 40
#define STAGE_HALVES (2 * 128 * AST)
#define STAGE_BYTES  (STAGE_HALVES * 2)
#define SMEM2_BYTES  (3 * STAGE_BYTES)

__global__ __launch_bounds__(256, 2) void mlp2_kernel(
    const float* __restrict__ b2, float* __restrict__ out)
{
    extern __shared__ __half sm2[];
    uint32_t smem_base = smem_u32(sm2);

    int tid = threadIdx.x;
    int wid = tid >> 5, lane = tid & 31;
    int bn = blockIdx.x, bm = blockIdx.y;
    const __half* Ag = g_h   + (size_t)bm * 128 * 512;
    const __half* Bg = g_w2h + (size_t)bn * 128 * 512;

    auto load = [&](int kt, int s) {
        __half* dstA = sm2 + (size_t)s * STAGE_HALVES;
        #pragma unroll
        for (int i = 0; i < 2; i++) {
            int q = tid + i * 256;
            int r = q >> 2, cc = q & 3;
            cp16(dstA + r * AST + cc * 8, Ag + (size_t)r * 512 + kt * 32 + cc * 8);
        }
        __half* dstB = dstA + 128 * AST;
        #pragma unroll
        for (int i = 0; i < 2; i++) {
            int q = tid + i * 256;
            int r = q >> 2, cc = q & 3;
            cp16(dstB + r * AST + cc * 8, Bg + (size_t)r * 512 + kt * 32 + cc * 8);
        }
    };

    load(0, 0); cp_commit();
    load(1, 1); cp_commit();

    int wm = wid & 3, wn = wid >> 2;
    int g = lane >> 2, t4 = lane & 3;
    int lrow = lane & 15, lcol = (lane >> 4) * 8;

    float c[2][8][4] = {};

    for (int kt = 0; kt < 16; kt++) {
        if (kt < 15) cp_wait<1>(); else cp_wait<0>();
        __syncthreads();                       // stage kt visible; stage (kt+2)%3 free
        if (kt + 2 < 16) { load(kt + 2, (kt + 2) % 3); cp_commit(); }

        uint32_t base = smem_base + (uint32_t)((kt % 3) * STAGE_BYTES);

        #pragma unroll
        for (int ks = 0; ks < 2; ks++) {
            uint32_t a[2][4];
            #pragma unroll
            for (int mf = 0; mf < 2; mf++) {
                uint32_t ad = base + ((wm * 32 + mf * 16 + lrow) * AST + ks * 16 + lcol) * 2;
                ldsm_x4(a[mf][0], a[mf][1], a[mf][2], a[mf][3], ad);
            }
            uint32_t b[4][4];
            #pragma unroll
            for (int nq = 0; nq < 4; nq++) {
                uint32_t bd = base + 128 * AST * 2 +
                              ((wn * 64 + nq * 16 + lrow) * AST + ks * 16 + lcol) * 2;
                ldsm_x4(b[nq][0], b[nq][1], b[nq][2], b[nq][3], bd);
            }
            #pragma unroll
            for (int mf = 0; mf < 2; mf++)
                #pragma unroll
                for (int nq = 0; nq < 4; nq++) {
                    mma16816(c[mf][nq * 2 + 0], a[mf], b[nq][0], b[nq][2]);
                    mma16816(c[mf][nq * 2 + 1], a[mf], b[nq][1], b[nq][3]);
                }
        }
    }

    #pragma unroll
    for (int mf = 0; mf < 2; mf++) {
        #pragma unroll
        for (int nf = 0; nf < 8; nf++) {
            int row = bm * 128 + wm * 32 + mf * 16 + g;
            int col = bn * 128 + wn * 64 + nf * 8 + 2 * t4;
            float2 bbv = *(const float2*)(b2 + col);
            float2 v0 = make_float2(c[mf][nf][0] + bbv.x, c[mf][nf][1] + bbv.y);
            float2 v1 = make_float2(c[mf][nf][2] + bbv.x, c[mf][nf][3] + bbv.y);
            *(float2*)(out + (size_t)row * 512 + col) = v0;
            *(float2*)(out + (size_t)(row + 8) * 512 + col) = v1;
        }
    }
}

// ---------------- launch ----------------
extern "C" void kernel_launch(void* const* d_in, const int* in_sizes, int n_in,
                              void* d_out, int out_size)
{
    const float* xyzt  = (const float*)d_in[0];
    const int*   smask = (const int*)d_in[1];
    const int*   tmask = (const int*)d_in[2];
    const float* stab  = (const float*)d_in[3];
    const float* ttab  = (const float*)d_in[4];
    const float* w1    = (const float*)d_in[5];
    const float* b1    = (const float*)d_in[6];
    const float* lng   = (const float*)d_in[7];
    const float* lnb   = (const float*)d_in[8];
    const float* w2    = (const float*)d_in[9];
    const float* b2    = (const float*)d_in[10];
    float*       out   = (float*)d_out;

    cudaFuncSetAttribute(mlp1_kernel, cudaFuncAttributeMaxDynamicSharedMemorySize,
                         M1_SMEM_BYTES);
    cudaFuncSetAttribute(mlp2_kernel, cudaFuncAttributeMaxDynamicSharedMemorySize,
                         SMEM2_BYTES);

    dim3 tb(32, 32);
    prep_weights_kernel<<<280, tb>>>(w2, w1);   // 256 w2-tiles + 24 w1-blocks
    encode_kernel<<<B_PTS / 256, 256>>>((const float4*)xyzt, smask, tmask,
                                        (const float2*)stab, (const float2*)ttab);
    mlp1_kernel<<<B_PTS / 32, 256, M1_SMEM_BYTES>>>(b1, lng, lnb);
    dim3 g2(HIDDEN / 128, B_PTS / 128);
    mlp2_kernel<<<g2, 256, SMEM2_BYTES>>>(b2, out);
}

// round 17
// speedup vs baseline: 2.4108x; 1.1145x over previous
#include <cuda_runtime.h>
#include <cuda_fp16.h>
#include <cstdint>
#include <math.h>

#define B_PTS   262144
#define HIDDEN  512
#define DIM_IN  48

// ---------------- scratch (static device arrays; no allocs) ----------------
__device__ __half g_feats[(size_t)B_PTS * DIM_IN];          // 24 MB fp16
__device__ __half g_h[(size_t)B_PTS * HIDDEN];              // 256 MB fp16
__device__ __half g_w2h[HIDDEN * HIDDEN];                   // [N][K] K-major fp16
__device__ __half g_w1h[HIDDEN * DIM_IN];                   // [N=512][K=48] fp16

__constant__ float c_sres[16] = {16,22,30,42,58,80,111,154,212,294,406,561,776,1072,1482,2048};
__constant__ float c_tres[8]  = {8,16,32,64,128,256,512,1024};

__device__ __forceinline__ void cp16(void* s, const void* g) {
    uint32_t sa = (uint32_t)__cvta_generic_to_shared(s);
    asm volatile("cp.async.cg.shared.global [%0], [%1], 16;" :: "r"(sa), "l"(g));
}
__device__ __forceinline__ void cp_commit() { asm volatile("cp.async.commit_group;"); }
template<int N> __device__ __forceinline__ void cp_wait() {
    asm volatile("cp.async.wait_group %0;" :: "n"(N));
}
__device__ __forceinline__ uint32_t smem_u32(const void* p) {
    return (uint32_t)__cvta_generic_to_shared(p);
}
__device__ __forceinline__ void ldsm_x4(uint32_t& r0, uint32_t& r1, uint32_t& r2, uint32_t& r3,
                                        uint32_t addr) {
    asm volatile("ldmatrix.sync.aligned.m8n8.x4.shared.b16 {%0,%1,%2,%3}, [%4];"
                 : "=r"(r0), "=r"(r1), "=r"(r2), "=r"(r3) : "r"(addr));
}
__device__ __forceinline__ void mma16816(float* c, const uint32_t* a, uint32_t b0, uint32_t b1) {
    asm volatile(
        "mma.sync.aligned.m16n8k16.row.col.f32.f16.f16.f32 "
        "{%0,%1,%2,%3},{%4,%5,%6,%7},{%8,%9},{%0,%1,%2,%3};"
        : "+f"(c[0]), "+f"(c[1]), "+f"(c[2]), "+f"(c[3])
        : "r"(a[0]), "r"(a[1]), "r"(a[2]), "r"(a[3]), "r"(b0), "r"(b1));
}
// tanh-form GELU with HW MUFU tanh: ~7 inst vs ~18 for erff path.
__device__ __forceinline__ float gelu_fast(float y) {
    float u = 0.7978845608028654f * fmaf(0.044715f * y, y * y, y);
    float t;
    asm("tanh.approx.f32 %0, %1;" : "=f"(t) : "f"(u));
    return 0.5f * y * (1.0f + t);
}

// ---------------- kernel 0: prep both weights (w2 transpose + w1 transpose) --------
__global__ void prep_weights_kernel(const float* __restrict__ w2,
                                    const float* __restrict__ w1) {
    __shared__ float tile[32][33];
    int b = blockIdx.x;
    if (b < 256) {                 // w2: 16x16 tiles of 32x32
        int bx = b & 15, by = b >> 4;
        int x = bx * 32 + threadIdx.x;   // n
        int y = by * 32 + threadIdx.y;   // k
        tile[threadIdx.y][threadIdx.x] = w2[y * 512 + x];
        __syncthreads();
        int ko = by * 32 + threadIdx.x;
        int no = bx * 32 + threadIdx.y;
        g_w2h[no * 512 + ko] = __float2half_rn(tile[threadIdx.x][threadIdx.y]);
    } else {                       // w1: 24 blocks x 1024 elems = 24576
        int i = (b - 256) * 1024 + threadIdx.y * 32 + threadIdx.x;
        int n = i / 48, k = i % 48;
        g_w1h[i] = __float2half_rn(w1[k * 512 + n]);
    }
}

// ---------------- kernel 1: 4D hash-grid encode -> fp16 feats ----------------
__global__ __launch_bounds__(256) void encode_kernel(
    const float4* __restrict__ xyzt,
    const int* __restrict__ smask,
    const int* __restrict__ tmask,
    const float2* __restrict__ stab,
    const float2* __restrict__ ttab)
{
    int i = blockIdx.x * 256 + threadIdx.x;
    float4 p = xyzt[i];
    float sm = smask[i] ? 1.0f : 0.0f;
    float tm = tmask[i] ? 1.0f : 0.0f;

    float out[DIM_IN];

    #pragma unroll
    for (int l = 0; l < 16; l++) {
        float r = c_sres[l];
        float px = p.x * r, py = p.y * r, pz = p.z * r;
        float fx = floorf(px), fy = floorf(py), fz = floorf(pz);
        unsigned bx = (unsigned)fx, by = (unsigned)fy, bz = (unsigned)fz;
        float wx1 = px - fx, wy1 = py - fy, wz1 = pz - fz;
        float wx0 = 1.0f - wx1, wy0 = 1.0f - wy1, wz0 = 1.0f - wz1;
        const float2* tab = stab + (size_t)l * 524288;
        unsigned hy0 = by * 2654435761u, hy1 = (by + 1u) * 2654435761u;
        unsigned hz0 = bz * 805459861u,  hz1 = (bz + 1u) * 805459861u;
        float f0 = 0.0f, f1 = 0.0f;
        #pragma unroll
        for (int cz = 0; cz < 2; cz++) {
            unsigned hz = cz ? hz1 : hz0; float wz = cz ? wz1 : wz0;
            #pragma unroll
            for (int cy = 0; cy < 2; cy++) {
                unsigned hy = cy ? hy1 : hy0; float wy = cy ? wy1 : wy0;
                #pragma unroll
                for (int cx = 0; cx < 2; cx++) {
                    unsigned idx = ((bx + (unsigned)cx) ^ hy ^ hz) & 524287u;
                    float w = (cx ? wx1 : wx0) * wy * wz;
                    float2 v = __ldg(tab + idx);
                    f0 += w * v.x;
                    f1 += w * v.y;
                }
            }
        }
        out[2 * l]     = f0 * sm;
        out[2 * l + 1] = f1 * sm;
    }

    #pragma unroll
    for (int l = 0; l < 8; l++) {
        float r = c_tres[l];
        float pt = p.w * r;
        float ft = floorf(pt);
        unsigned bt = (unsigned)ft;
        float w1v = pt - ft, w0v = 1.0f - w1v;
        const float2* tab = ttab + (size_t)l * 131072;
        float2 v0 = __ldg(tab + (bt & 131071u));
        float2 v1 = __ldg(tab + ((bt + 1u) & 131071u));
        out[32 + 2 * l]     = (w0v * v0.x + w1v * v1.x) * tm;
        out[32 + 2 * l + 1] = (w0v * v0.y + w1v * v1.y) * tm;
    }

    uint32_t w[24];
    #pragma unroll
    for (int j = 0; j < 24; j++) {
        __half2 h2 = __floats2half2_rn(out[2*j], out[2*j+1]);
        w[j] = *(uint32_t*)&h2;
    }
    uint4* dst = (uint4*)(g_feats + (size_t)i * DIM_IN);
    #pragma unroll
    for (int q = 0; q < 6; q++)
        dst[q] = make_uint4(w[4*q], w[4*q+1], w[4*q+2], w[4*q+3]);
}

// ---------------- kernel 2: GEMM1 (48->512) fp16 mma + LN + GELU -> fp16 h ----------
#define KP 56
#define M1_SMEM_BYTES (512*KP*2 + 32*KP*2 + 32*8*8 + 256)
__global__ __launch_bounds__(256, 2) void mlp1_kernel(
    const float* __restrict__ b1,
    const float* __restrict__ lng, const float* __restrict__ lnb)
{
    extern __shared__ __align__(16) char sm1[];
    __half* w1s = (__half*)sm1;               // [512][KP]
    __half* fs  = w1s + 512 * KP;             // [32][KP]
    float2* red = (float2*)(fs + 32 * KP);    // [32][8]
    float*  mus = (float*)(red + 32 * 8);
    float*  rss = mus + 32;
    __half* hstage = (__half*)sm1;            // overlay w1s after mainloop: [32][520]

    int tid = threadIdx.x;
    int wid = tid >> 5, lane = tid & 31;

    for (int q = tid; q < 3072; q += 256) {
        int r = q / 6, cc = q % 6;
        cp16(w1s + r * KP + cc * 8, g_w1h + r * 48 + cc * 8);
    }
    {
        const __half* fg = g_feats + (size_t)blockIdx.x * 32 * 48;
        if (tid < 192) {
            int r = tid / 6, cc = tid % 6;
            cp16(fs + r * KP + cc * 8, fg + r * 48 + cc * 8);
        }
    }
    cp_commit(); cp_wait<0>();
    __syncthreads();

    int g = lane >> 2, t4 = lane & 3;
    int lrow = lane & 15, lcol = (lane >> 4) * 8;
    uint32_t fsb = smem_u32(fs), wsb = smem_u32(w1s);

    float c[2][8][4] = {};

    #pragma unroll
    for (int ks = 0; ks < 3; ks++) {
        uint32_t a[2][4];
        #pragma unroll
        for (int mf = 0; mf < 2; mf++) {
            uint32_t ad = fsb + (uint32_t)(((mf * 16 + lrow) * KP + ks * 16 + lcol) * 2);
            ldsm_x4(a[mf][0], a[mf][1], a[mf][2], a[mf][3], ad);
        }
        uint32_t b[4][4];
        #pragma unroll
        for (int nq = 0; nq < 4; nq++) {
            uint32_t bd = wsb + (uint32_t)(((wid * 64 + nq * 16 + lrow) * KP + ks * 16 + lcol) * 2);
            ldsm_x4(b[nq][0], b[nq][1], b[nq][2], b[nq][3], bd);
        }
        #pragma unroll
        for (int mf = 0; mf < 2; mf++)
            #pragma unroll
            for (int nq = 0; nq < 4; nq++) {
                mma16816(c[mf][nq * 2 + 0], a[mf], b[nq][0], b[nq][2]);
                mma16816(c[mf][nq * 2 + 1], a[mf], b[nq][1], b[nq][3]);
            }
    }

    #pragma unroll
    for (int nf = 0; nf < 8; nf++) {
        int col = wid * 64 + nf * 8 + 2 * t4;
        float2 bbv = *(const float2*)(b1 + col);
        #pragma unroll
        for (int mf = 0; mf < 2; mf++) {
            c[mf][nf][0] += bbv.x; c[mf][nf][1] += bbv.y;
            c[mf][nf][2] += bbv.x; c[mf][nf][3] += bbv.y;
        }
    }

    {
        float s[4] = {0,0,0,0}, s2[4] = {0,0,0,0};
        #pragma unroll
        for (int nf = 0; nf < 8; nf++) {
            #pragma unroll
            for (int mf = 0; mf < 2; mf++) {
                float v0 = c[mf][nf][0], v1 = c[mf][nf][1];
                float v2 = c[mf][nf][2], v3 = c[mf][nf][3];
                s[mf*2+0] += v0 + v1;  s2[mf*2+0] += v0*v0 + v1*v1;
                s[mf*2+1] += v2 + v3;  s2[mf*2+1] += v2*v2 + v3*v3;
            }
        }
        #pragma unroll
        for (int r = 0; r < 4; r++) {
            #pragma unroll
            for (int off = 1; off < 4; off <<= 1) {
                s[r]  += __shfl_xor_sync(0xffffffffu, s[r],  off);
                s2[r] += __shfl_xor_sync(0xffffffffu, s2[r], off);
            }
        }
        if (t4 == 0) {
            red[(g     ) * 8 + wid] = make_float2(s[0], s2[0]);
            red[(g + 8 ) * 8 + wid] = make_float2(s[1], s2[1]);
            red[(g + 16) * 8 + wid] = make_float2(s[2], s2[2]);
            red[(g + 24) * 8 + wid] = make_float2(s[3], s2[3]);
        }
    }
    __syncthreads();
    if (tid < 32) {
        float s = 0.0f, s2 = 0.0f;
        #pragma unroll
        for (int j = 0; j < 8; j++) {
            float2 v = red[tid * 8 + j];
            s += v.x; s2 += v.y;
        }
        float mu = s * (1.0f / 512.0f);
        float var = s2 * (1.0f / 512.0f) - mu * mu;
        mus[tid] = mu;
        rss[tid] = rsqrtf(var + 1e-5f);
    }
    __syncthreads();   // ldmatrix reads of w1s done -> safe to overlay

    {
        float mu[4], rs[4];
        #pragma unroll
        for (int r = 0; r < 4; r++) { mu[r] = mus[g + 8*r]; rs[r] = rss[g + 8*r]; }
        #pragma unroll
        for (int nf = 0; nf < 8; nf++) {
            int col = wid * 64 + nf * 8 + 2 * t4;
            float2 lgv = *(const float2*)(lng + col);
            float2 lbv = *(const float2*)(lnb + col);
            #pragma unroll
            for (int mf = 0; mf < 2; mf++) {
                int r0 = mf * 2, r1 = mf * 2 + 1;
                float y0 = (c[mf][nf][0] - mu[r0]) * rs[r0] * lgv.x + lbv.x;
                float y1 = (c[mf][nf][1] - mu[r0]) * rs[r0] * lgv.y + lbv.y;
                float y2 = (c[mf][nf][2] - mu[r1]) * rs[r1] * lgv.x + lbv.x;
                float y3 = (c[mf][nf][3] - mu[r1]) * rs[r1] * lgv.y + lbv.y;
                __half2 h0 = __floats2half2_rn(gelu_fast(y0), gelu_fast(y1));
                __half2 h1 = __floats2half2_rn(gelu_fast(y2), gelu_fast(y3));
                *(__half2*)(hstage + (mf * 16 + g) * 520 + col)     = h0;
                *(__half2*)(hstage + (mf * 16 + g + 8) * 520 + col) = h1;
            }
        }
    }
    __syncthreads();
    {
        uint4* hout = (uint4*)(g_h + (size_t)blockIdx.x * 32 * 512);
        #pragma unroll
        for (int i = 0; i < 8; i++) {
            int q = tid + i * 256;
            int r = q >> 6, cc = q & 63;
            hout[q] = *(uint4*)(hstage + r * 520 + cc * 8);
        }
    }
}

// ---------------- kernel 3: GEMM2 (512x512) fp16 mma — R9 pipeline (proven) -------
#define AST 40
#define STAGE_HALVES (2 * 128 * AST)
#define STAGE_BYTES  (STAGE_HALVES * 2)
#define SMEM2_BYTES  (3 * STAGE_BYTES)

__global__ __launch_bounds__(256, 2) void mlp2_kernel(
    const float* __restrict__ b2, float* __restrict__ out)
{
    extern __shared__ __half sm2[];
    uint32_t smem_base = smem_u32(sm2);

    int tid = threadIdx.x;
    int wid = tid >> 5, lane = tid & 31;
    int bn = blockIdx.x, bm = blockIdx.y;
    const __half* Ag = g_h   + (size_t)bm * 128 * 512;
    const __half* Bg = g_w2h + (size_t)bn * 128 * 512;

    auto load = [&](int kt, int s) {
        __half* dstA = sm2 + (size_t)s * STAGE_HALVES;
        #pragma unroll
        for (int i = 0; i < 2; i++) {
            int q = tid + i * 256;
            int r = q >> 2, cc = q & 3;
            cp16(dstA + r * AST + cc * 8, Ag + (size_t)r * 512 + kt * 32 + cc * 8);
        }
        __half* dstB = dstA + 128 * AST;
        #pragma unroll
        for (int i = 0; i < 2; i++) {
            int q = tid + i * 256;
            int r = q >> 2, cc = q & 3;
            cp16(dstB + r * AST + cc * 8, Bg + (size_t)r * 512 + kt * 32 + cc * 8);
        }
    };

    load(0, 0); cp_commit();
    load(1, 1); cp_commit();

    int wm = wid & 3, wn = wid >> 2;
    int g = lane >> 2, t4 = lane & 3;
    int lrow = lane & 15, lcol = (lane >> 4) * 8;

    float c[2][8][4] = {};

    for (int kt = 0; kt < 16; kt++) {
        if (kt < 15) cp_wait<1>(); else cp_wait<0>();
        __syncthreads();                       // stage kt visible; stage (kt+2)%3 free
        if (kt + 2 < 16) { load(kt + 2, (kt + 2) % 3); cp_commit(); }

        uint32_t base = smem_base + (uint32_t)((kt % 3) * STAGE_BYTES);

        #pragma unroll
        for (int ks = 0; ks < 2; ks++) {
            uint32_t a[2][4];
            #pragma unroll
            for (int mf = 0; mf < 2; mf++) {
                uint32_t ad = base + ((wm * 32 + mf * 16 + lrow) * AST + ks * 16 + lcol) * 2;
                ldsm_x4(a[mf][0], a[mf][1], a[mf][2], a[mf][3], ad);
            }
            uint32_t b[4][4];
            #pragma unroll
            for (int nq = 0; nq < 4; nq++) {
                uint32_t bd = base + 128 * AST * 2 +
                              ((wn * 64 + nq * 16 + lrow) * AST + ks * 16 + lcol) * 2;
                ldsm_x4(b[nq][0], b[nq][1], b[nq][2], b[nq][3], bd);
            }
            #pragma unroll
            for (int mf = 0; mf < 2; mf++)
                #pragma unroll
                for (int nq = 0; nq < 4; nq++) {
                    mma16816(c[mf][nq * 2 + 0], a[mf], b[nq][0], b[nq][2]);
                    mma16816(c[mf][nq * 2 + 1], a[mf], b[nq][1], b[nq][3]);
                }
        }
    }

    #pragma unroll
    for (int mf = 0; mf < 2; mf++) {
        #pragma unroll
        for (int nf = 0; nf < 8; nf++) {
            int row = bm * 128 + wm * 32 + mf * 16 + g;
            int col = bn * 128 + wn * 64 + nf * 8 + 2 * t4;
            float2 bbv = *(const float2*)(b2 + col);
            float2 v0 = make_float2(c[mf][nf][0] + bbv.x, c[mf][nf][1] + bbv.y);
            float2 v1 = make_float2(c[mf][nf][2] + bbv.x, c[mf][nf][3] + bbv.y);
            *(float2*)(out + (size_t)row * 512 + col) = v0;
            *(float2*)(out + (size_t)(row + 8) * 512 + col) = v1;
        }
    }
}

// ---------------- launch ----------------
extern "C" void kernel_launch(void* const* d_in, const int* in_sizes, int n_in,
                              void* d_out, int out_size)
{
    const float* xyzt  = (const float*)d_in[0];
    const int*   smask = (const int*)d_in[1];
    const int*   tmask = (const int*)d_in[2];
    const float* stab  = (const float*)d_in[3];
    const float* ttab  = (const float*)d_in[4];
    const float* w1    = (const float*)d_in[5];
    const float* b1    = (const float*)d_in[6];
    const float* lng   = (const float*)d_in[7];
    const float* lnb   = (const float*)d_in[8];
    const float* w2    = (const float*)d_in[9];
    const float* b2    = (const float*)d_in[10];
    float*       out   = (float*)d_out;

    cudaFuncSetAttribute(mlp1_kernel, cudaFuncAttributeMaxDynamicSharedMemorySize,
                         M1_SMEM_BYTES);
    cudaFuncSetAttribute(mlp2_kernel, cudaFuncAttributeMaxDynamicSharedMemorySize,
                         SMEM2_BYTES);

    dim3 tb(32, 32);
    prep_weights_kernel<<<280, tb>>>(w2, w1);   // 256 w2-tiles + 24 w1-blocks
    encode_kernel<<<B_PTS / 256, 256>>>((const float4*)xyzt, smask, tmask,
                                        (const float2*)stab, (const float2*)ttab);
    mlp1_kernel<<<B_PTS / 32, 256, M1_SMEM_BYTES>>>(b1, lng, lnb);
    dim3 g2(HIDDEN / 128, B_PTS / 128);
    mlp2_kernel<<<g2, 256, SMEM2_BYTES>>>(b2, out);
}